// round 1
// baseline (speedup 1.0000x reference)
#include <cuda_runtime.h>
#include <cuda_bf16.h>

// SSD default-box decode. 5 feature levels, shapes (B=32, h, w, A=6, D=85),
// only channels [0:4) are used. Output is the concatenation over levels of
// (B, h, w, A, 4) float32.
//
// Per anchor (level l, spatial (y,x), aspect a, coords c0..c3):
//   cx = (x+0.5)/w*512 ; cy = (y+0.5)/h*512
//   bw = s*512*sqrt(ar[a]) ; bh = s*512/sqrt(ar[a])
//   px = cx + bh*c0 ; py = cy + bw*c1 ; pw = bw*exp(c2) ; ph = bh*exp(c3)
//   out = (px*w/512, py*h/512, pw*w/512, ph*h/512)
// (note px uses bh and py uses bw, exactly as the reference does)

#define A_RATIOS 6
#define N_LVL 5

// anchor-count prefix sums (incl. batch=32):
//   L0: 32*64*64*6 = 786432
//   L1: 32*32*32*6 = 196608  -> cum 983040
//   L2: 32*16*16*6 = 49152   -> cum 1032192
//   L3: 32*8*8*6   = 12288   -> cum 1044480
//   L4: 32*4*4*6   = 3072    -> cum 1047552
#define TOTAL_ANCHORS 1047552

__constant__ float c_ar[A_RATIOS] = {1.0f, 2.0f, 0.5f, 3.0f, 0.3333333f, 1.2f};
__constant__ float c_scale[N_LVL] = {0.1f, 0.2f, 0.375f, 0.55f, 0.725f};

__global__ __launch_bounds__(256) void ssd_decode_kernel(
    const float* __restrict__ f0,
    const float* __restrict__ f1,
    const float* __restrict__ f2,
    const float* __restrict__ f3,
    const float* __restrict__ f4,
    float4* __restrict__ out)
{
    int idx = blockIdx.x * blockDim.x + threadIdx.x;
    if (idx >= TOTAL_ANCHORS) return;

    // --- level lookup (constant-folded branches; divergence only at 4 warp
    // boundaries out of 32736 warps) ---
    int lvl, base, wlog;
    const float* __restrict__ in;
    if (idx < 786432)        { lvl = 0; base = 0;       wlog = 6; in = f0; }
    else if (idx < 983040)   { lvl = 1; base = 786432;  wlog = 5; in = f1; }
    else if (idx < 1032192)  { lvl = 2; base = 983040;  wlog = 4; in = f2; }
    else if (idx < 1044480)  { lvl = 3; base = 1032192; wlog = 3; in = f3; }
    else                     { lvl = 4; base = 1044480; wlog = 2; in = f4; }

    int local = idx - base;

    // decompose: local = ((b*h + y)*w + x)*6 + a   (h == w == 1<<wlog)
    int a = local % A_RATIOS;
    int t = local / A_RATIOS;
    int wm = (1 << wlog) - 1;
    int x = t & wm;
    int y = (t >> wlog) & wm;

    // --- load the 4 coord floats (row base = local*85 floats; 4B-aligned only,
    // so scalar loads) ---
    const float* row = in + (long long)local * 85;
    float c0 = __ldg(row + 0);
    float c1 = __ldg(row + 1);
    float c2 = __ldg(row + 2);
    float c3 = __ldg(row + 3);

    // --- default box + decode, matching reference op-for-op ---
    float wf   = (float)(1 << wlog);
    float inv  = 512.0f / wf;          // exact (powers of two)
    float sxy  = wf * (1.0f / 512.0f); // exact

    float s  = c_scale[lvl];
    float q  = sqrtf(c_ar[a]);
    float bw = s * 512.0f * q;
    float bh = s * 512.0f / q;

    float cx = ((float)x + 0.5f) * inv;
    float cy = ((float)y + 0.5f) * inv;

    float px = cx + bh * c0;
    float py = cy + bw * c1;
    float pw = bw * expf(c2);
    float ph = bh * expf(c3);

    out[idx] = make_float4(px * sxy, py * sxy, pw * sxy, ph * sxy);
}

extern "C" void kernel_launch(void* const* d_in, const int* in_sizes, int n_in,
                              void* d_out, int out_size)
{
    const float* f0 = (const float*)d_in[0];
    const float* f1 = (const float*)d_in[1];
    const float* f2 = (const float*)d_in[2];
    const float* f3 = (const float*)d_in[3];
    const float* f4 = (const float*)d_in[4];
    float4* out = (float4*)d_out;

    int threads = 256;
    int blocks = (TOTAL_ANCHORS + threads - 1) / threads; // 4092
    ssd_decode_kernel<<<blocks, threads>>>(f0, f1, f2, f3, f4, out);
}

// round 3
// speedup vs baseline: 1.0154x; 1.0154x over previous
#include <cuda_runtime.h>
#include <cuda_bf16.h>

// SSD default-box decode. 5 feature levels, shapes (B=32, h, w, A=6, D=85),
// only channels [0:4) are used. Output is the concatenation over levels of
// (B, h, w, A, 4) float32.
//
// R1/R2 change: coord loads via ld.global.cg (L2-only, 32B-sector fills)
// instead of __ldg/.nc, to kill the 128B line-fill read amplification seen in
// ncu (157 MB DRAM traffic vs 63 MB true footprint). R2 is a resubmit after
// an infra-side container failure; asm no longer volatile so ptxas can batch.

#define A_RATIOS 6
#define N_LVL 5
#define TOTAL_ANCHORS 1047552

__constant__ float c_ar[A_RATIOS] = {1.0f, 2.0f, 0.5f, 3.0f, 0.3333333f, 1.2f};
__constant__ float c_scale[N_LVL] = {0.1f, 0.2f, 0.375f, 0.55f, 0.725f};

__device__ __forceinline__ float ldcg_f32(const float* p) {
    float v;
    asm("ld.global.cg.f32 %0, [%1];" : "=f"(v) : "l"(p));
    return v;
}

__global__ __launch_bounds__(256) void ssd_decode_kernel(
    const float* __restrict__ f0,
    const float* __restrict__ f1,
    const float* __restrict__ f2,
    const float* __restrict__ f3,
    const float* __restrict__ f4,
    float4* __restrict__ out)
{
    int idx = blockIdx.x * blockDim.x + threadIdx.x;
    if (idx >= TOTAL_ANCHORS) return;

    // --- level lookup (constant-folded branches; divergence only at 4 warp
    // boundaries out of 32736 warps) ---
    int lvl, base, wlog;
    const float* in;
    if (idx < 786432)        { lvl = 0; base = 0;       wlog = 6; in = f0; }
    else if (idx < 983040)   { lvl = 1; base = 786432;  wlog = 5; in = f1; }
    else if (idx < 1032192)  { lvl = 2; base = 983040;  wlog = 4; in = f2; }
    else if (idx < 1044480)  { lvl = 3; base = 1032192; wlog = 3; in = f3; }
    else                     { lvl = 4; base = 1044480; wlog = 2; in = f4; }

    int local = idx - base;

    // decompose: local = ((b*h + y)*w + x)*6 + a   (h == w == 1<<wlog)
    int a = local % A_RATIOS;
    int t = local / A_RATIOS;
    int wm = (1 << wlog) - 1;
    int x = t & wm;
    int y = (t >> wlog) & wm;

    // --- load the 4 coord floats (row base = local*85 floats; only 4B-aligned,
    // so scalar loads). .cg: fill L2 at sector granularity, skip L1 line fill. ---
    const float* row = in + (long long)local * 85;
    float c0 = ldcg_f32(row + 0);
    float c1 = ldcg_f32(row + 1);
    float c2 = ldcg_f32(row + 2);
    float c3 = ldcg_f32(row + 3);

    // --- default box + decode, matching reference op-for-op ---
    float wf   = (float)(1 << wlog);
    float inv  = 512.0f / wf;          // exact (powers of two)
    float sxy  = wf * (1.0f / 512.0f); // exact

    float s  = c_scale[lvl];
    float q  = sqrtf(c_ar[a]);
    float bw = s * 512.0f * q;
    float bh = s * 512.0f / q;

    float cx = ((float)x + 0.5f) * inv;
    float cy = ((float)y + 0.5f) * inv;

    float px = cx + bh * c0;
    float py = cy + bw * c1;
    float pw = bw * expf(c2);
    float ph = bh * expf(c3);

    out[idx] = make_float4(px * sxy, py * sxy, pw * sxy, ph * sxy);
}

extern "C" void kernel_launch(void* const* d_in, const int* in_sizes, int n_in,
                              void* d_out, int out_size)
{
    const float* f0 = (const float*)d_in[0];
    const float* f1 = (const float*)d_in[1];
    const float* f2 = (const float*)d_in[2];
    const float* f3 = (const float*)d_in[3];
    const float* f4 = (const float*)d_in[4];
    float4* out = (float4*)d_out;

    int threads = 256;
    int blocks = (TOTAL_ANCHORS + threads - 1) / threads; // 4092
    ssd_decode_kernel<<<blocks, threads>>>(f0, f1, f2, f3, f4, out);
}